// round 7
// baseline (speedup 1.0000x reference)
#include <cuda_runtime.h>
#include <cstdint>
#include <cstddef>
#include <math.h>

#define LVL   3
#define BSZ   128
#define T0    256
#define STOCH 128
#define DETER 1024
#define EMBED 512
#define OBS_D 512
#define G3    (3*DETER)   // 3072
#define NB    128          // persistent-kernel grid size (<= 148 SMs, all resident)

// ---------------------------------------------------------------------------
// Static device scratch (no allocations allowed).
// ---------------------------------------------------------------------------
__device__ float g_h[BSZ * EMBED];
__device__ float g_qh[BSZ * EMBED];
__device__ float g_sample[BSZ * STOCH];
__device__ float g_dets1[BSZ * 64 * DETER];       // level-1 dets (B, 64, 1024)
__device__ float g_dets2[BSZ * 16 * DETER];       // level-2 dets (B, 16, 1024)
__device__ float g_pre_ctx[BSZ * 64 * EMBED];     // ctx @ Wp_ctx  (per upper-level step)
__device__ float g_pre_obs[BSZ * T0 * EMBED];     // obs @ Wq_obs  (per step)
__device__ unsigned int g_bar_count;               // software grid barrier
__device__ unsigned int g_bar_gen;

// ---------------------------------------------------------------------------
// Software grid barrier (sense via monotonic generation counter).
// Safe because grid = NB = 128 blocks <= #SMs -> all blocks co-resident.
// ---------------------------------------------------------------------------
__device__ __forceinline__ void grid_sync() {
    __syncthreads();
    if (threadIdx.x == 0) {
        volatile unsigned int* genp = &g_bar_gen;
        unsigned int g = *genp;
        __threadfence();                         // release: my block's writes
        unsigned int a = atomicAdd(&g_bar_count, 1u);
        if (a == NB - 1u) {
            atomicExch(&g_bar_count, 0u);
            __threadfence();
            atomicAdd(&g_bar_gen, 1u);           // release barrier
        } else {
            while (*genp == g) { }               // spin on L2
        }
        __threadfence();                         // acquire
    }
    __syncthreads();
}

// ---------------------------------------------------------------------------
// Precompute GEMM: C[M,N] = A[M,K] @ W[K,N]   (no bias)
// BM=64, BN=64, BK=16, 128 threads, 4x8 register micro-tile.
// A rows contiguous with leading dim lda; W leading dim ldw; C leading dim ldc.
// ---------------------------------------------------------------------------
__global__ __launch_bounds__(128) void gemm64_kernel(
    const float* __restrict__ A, int lda,
    const float* __restrict__ W, int ldw,
    float* __restrict__ C, int ldc, int K)
{
    constexpr int BM = 64, BN = 64, BK = 16, TM = 4, TN = 8;
    __shared__ float sA[BK][BM + 4];
    __shared__ float sW[BK][BN];

    const int tid  = threadIdx.x;
    const int tx   = tid & 7;
    const int ty   = tid >> 3;
    const int row0 = blockIdx.y * BM;
    const int col0 = blockIdx.x * BN;

    float acc[TM][TN];
    #pragma unroll
    for (int i = 0; i < TM; i++)
        #pragma unroll
        for (int j = 0; j < TN; j++) acc[i][j] = 0.0f;

    for (int k0 = 0; k0 < K; k0 += BK) {
        #pragma unroll
        for (int p = 0; p < 8; p++) {
            int i  = tid + p * 128;
            int kk = i & 15, r = i >> 4;
            sA[kk][r] = A[(size_t)(row0 + r) * lda + (k0 + kk)];
        }
        #pragma unroll
        for (int p = 0; p < 8; p++) {
            int i  = tid + p * 128;
            int kk = i >> 6, cc = i & 63;
            sW[kk][cc] = W[(size_t)(k0 + kk) * ldw + (col0 + cc)];
        }
        __syncthreads();
        #pragma unroll
        for (int kk = 0; kk < BK; kk++) {
            float4 av = *(const float4*)&sA[kk][ty * TM];
            float4 w0 = *(const float4*)&sW[kk][tx * TN];
            float4 w1 = *(const float4*)&sW[kk][tx * TN + 4];
            float a[TM] = {av.x, av.y, av.z, av.w};
            float w[TN] = {w0.x, w0.y, w0.z, w0.w, w1.x, w1.y, w1.z, w1.w};
            #pragma unroll
            for (int i = 0; i < TM; i++)
                #pragma unroll
                for (int j = 0; j < TN; j++)
                    acc[i][j] = fmaf(a[i], w[j], acc[i][j]);
        }
        __syncthreads();
    }

    #pragma unroll
    for (int i = 0; i < TM; i++) {
        int m  = row0 + ty * TM + i;
        int n0 = col0 + tx * TN;
        float4 o0 = {acc[i][0], acc[i][1], acc[i][2], acc[i][3]};
        float4 o1 = {acc[i][4], acc[i][5], acc[i][6], acc[i][7]};
        *(float4*)&C[(size_t)m * ldc + n0]     = o0;
        *(float4*)&C[(size_t)m * ldc + n0 + 4] = o1;
    }
}

// ---------------------------------------------------------------------------
// Persistent per-level scan kernel. Grid = NB blocks x 256 threads.
// Per step t (4 phases, grid barriers between):
//   P1: h = relu(sample @ Wp_s + bp + pre_ctx[b, t % T1])        (128x512, K=128)
//   P2: gi = h @ Wih + bih ; gh = det_old @ Whh + bhh ; GRU combine -> det_new
//       (block owns 32 rows x 32 gate-cols across all 3 gates of BOTH gi, gh)
//   P3: qh = relu(det_new @ Wq_det + bq + pre_obs[b, t])          (128x512, K=1024)
//   P4: sample = qh @ Wqm + bqm                                   (128x128, K=512)
// ---------------------------------------------------------------------------
__global__ __launch_bounds__(256, 1) void level_kernel(
    float* __restrict__ dets, int T,
    const float* __restrict__ pre_ctx, int T1,
    const float* __restrict__ pre_obs,
    const float* __restrict__ Wp,  const float* __restrict__ bp,
    const float* __restrict__ Wih, const float* __restrict__ Whh,
    const float* __restrict__ bih, const float* __restrict__ bhh,
    const float* __restrict__ Wq,  const float* __restrict__ bq,
    const float* __restrict__ Wqm, const float* __restrict__ bqm)
{
    __shared__ float smem[32 * 36 + 32 * 96];
    float (*sA)[36] = (float(*)[36])smem;             // 32 x 36
    float (*sW)[96] = (float(*)[96])(smem + 32 * 36); // 32 x 96

    const int tid = threadIdx.x;
    const int bid = blockIdx.x;
    const int rg  = tid >> 5;      // 0..7
    const int c   = tid & 31;      // 0..31
    const size_t ldd = (size_t)T * DETER;   // row stride between batches in dets

    for (int t = 0; t < T; t++) {
        // ======================= P1: h ====================================
        {
            const int m0 = (bid & 7) * 16;
            const int n0 = (bid >> 3) * 32;
            float a0 = 0.0f, a1 = 0.0f;
            if (t > 0) {
                for (int k0 = 0; k0 < STOCH; k0 += 32) {
                    #pragma unroll
                    for (int p = 0; p < 2; p++) {
                        int idx = tid + p * 256;
                        int kk = idx & 31, r = idx >> 5;
                        sA[kk][r] = g_sample[(m0 + r) * STOCH + k0 + kk];
                    }
                    #pragma unroll
                    for (int p = 0; p < 4; p++) {
                        int idx = tid + p * 256;
                        int kk = idx >> 5, cc = idx & 31;
                        sW[kk][cc] = Wp[(size_t)(k0 + kk) * EMBED + n0 + cc];
                    }
                    __syncthreads();
                    #pragma unroll
                    for (int kk = 0; kk < 32; kk++) {
                        float2 av = *(const float2*)&sA[kk][rg * 2];
                        float  w  = sW[kk][c];
                        a0 = fmaf(av.x, w, a0);
                        a1 = fmaf(av.y, w, a1);
                    }
                    __syncthreads();
                }
            }
            const int n = n0 + c;
            const float base = bp[n];
            #pragma unroll
            for (int i = 0; i < 2; i++) {
                int m = m0 + rg * 2 + i;
                float pc = pre_ctx ? pre_ctx[((size_t)m * T1 + (t % T1)) * EMBED + n] : 0.0f;
                float v = (i == 0 ? a0 : a1) + base + pc;
                g_h[m * EMBED + n] = fmaxf(v, 0.0f);
            }
        }
        grid_sync();

        // ============ P2: gates (gi & gh) + GRU combine ====================
        {
            const int m0 = (bid & 3) * 32;
            const int j0 = (bid >> 2) * 32;
            float ai[3][4], ah[3][4];
            #pragma unroll
            for (int s = 0; s < 3; s++)
                #pragma unroll
                for (int i = 0; i < 4; i++) { ai[s][i] = 0.0f; ah[s][i] = 0.0f; }

            // gi = h @ Wih  (K = 512)
            for (int k0 = 0; k0 < EMBED; k0 += 32) {
                #pragma unroll
                for (int p = 0; p < 4; p++) {
                    int idx = tid + p * 256;
                    int kk = idx & 31, r = idx >> 5;
                    sA[kk][r] = g_h[(m0 + r) * EMBED + k0 + kk];
                }
                #pragma unroll
                for (int seg = 0; seg < 3; seg++)
                    #pragma unroll
                    for (int p = 0; p < 4; p++) {
                        int idx = tid + p * 256;
                        int kk = idx >> 5, cc = idx & 31;
                        sW[kk][seg * 32 + cc] =
                            Wih[(size_t)(k0 + kk) * G3 + seg * DETER + j0 + cc];
                    }
                __syncthreads();
                #pragma unroll
                for (int kk = 0; kk < 32; kk++) {
                    float4 av = *(const float4*)&sA[kk][rg * 4];
                    #pragma unroll
                    for (int seg = 0; seg < 3; seg++) {
                        float w = sW[kk][seg * 32 + c];
                        ai[seg][0] = fmaf(av.x, w, ai[seg][0]);
                        ai[seg][1] = fmaf(av.y, w, ai[seg][1]);
                        ai[seg][2] = fmaf(av.z, w, ai[seg][2]);
                        ai[seg][3] = fmaf(av.w, w, ai[seg][3]);
                    }
                }
                __syncthreads();
            }

            // gh = det_old @ Whh  (K = 1024); skipped when det_old == 0 (t==0)
            if (t > 0) {
                const float* detp = dets + (size_t)(t - 1) * DETER;
                for (int k0 = 0; k0 < DETER; k0 += 32) {
                    #pragma unroll
                    for (int p = 0; p < 4; p++) {
                        int idx = tid + p * 256;
                        int kk = idx & 31, r = idx >> 5;
                        sA[kk][r] = detp[(size_t)(m0 + r) * ldd + k0 + kk];
                    }
                    #pragma unroll
                    for (int seg = 0; seg < 3; seg++)
                        #pragma unroll
                        for (int p = 0; p < 4; p++) {
                            int idx = tid + p * 256;
                            int kk = idx >> 5, cc = idx & 31;
                            sW[kk][seg * 32 + cc] =
                                Whh[(size_t)(k0 + kk) * G3 + seg * DETER + j0 + cc];
                        }
                    __syncthreads();
                    #pragma unroll
                    for (int kk = 0; kk < 32; kk++) {
                        float4 av = *(const float4*)&sA[kk][rg * 4];
                        #pragma unroll
                        for (int seg = 0; seg < 3; seg++) {
                            float w = sW[kk][seg * 32 + c];
                            ah[seg][0] = fmaf(av.x, w, ah[seg][0]);
                            ah[seg][1] = fmaf(av.y, w, ah[seg][1]);
                            ah[seg][2] = fmaf(av.z, w, ah[seg][2]);
                            ah[seg][3] = fmaf(av.w, w, ah[seg][3]);
                        }
                    }
                    __syncthreads();
                }
            }

            // GRU combine epilogue -> det_new (written straight into dets/d_out)
            float* dnew = dets + (size_t)t * DETER;
            const float* dold = dets + (size_t)(t - 1) * DETER;
            const int j = j0 + c;
            const float bi_r = bih[j],             bh_r = bhh[j];
            const float bi_z = bih[DETER + j],     bh_z = bhh[DETER + j];
            const float bi_n = bih[2 * DETER + j], bh_n = bhh[2 * DETER + j];
            #pragma unroll
            for (int i = 0; i < 4; i++) {
                int m = m0 + rg * 4 + i;
                float gr  = ai[0][i] + bi_r + ah[0][i] + bh_r;
                float gz  = ai[1][i] + bi_z + ah[1][i] + bh_z;
                float inn = ai[2][i] + bi_n;
                float hn  = ah[2][i] + bh_n;
                float rr = 1.0f / (1.0f + expf(-gr));
                float zz = 1.0f / (1.0f + expf(-gz));
                float nn = tanhf(inn + rr * hn);
                float d  = (t > 0) ? dold[(size_t)m * ldd + j] : 0.0f;
                dnew[(size_t)m * ldd + j] = (1.0f - zz) * nn + zz * d;
            }
        }
        grid_sync();

        // ======================= P3: qh ====================================
        {
            const int m0 = (bid & 7) * 16;
            const int n0 = (bid >> 3) * 32;
            float a0 = 0.0f, a1 = 0.0f;
            const float* dnew = dets + (size_t)t * DETER;
            for (int k0 = 0; k0 < DETER; k0 += 32) {
                #pragma unroll
                for (int p = 0; p < 2; p++) {
                    int idx = tid + p * 256;
                    int kk = idx & 31, r = idx >> 5;
                    sA[kk][r] = dnew[(size_t)(m0 + r) * ldd + k0 + kk];
                }
                #pragma unroll
                for (int p = 0; p < 4; p++) {
                    int idx = tid + p * 256;
                    int kk = idx >> 5, cc = idx & 31;
                    sW[kk][cc] = Wq[(size_t)(k0 + kk) * EMBED + n0 + cc];
                }
                __syncthreads();
                #pragma unroll
                for (int kk = 0; kk < 32; kk++) {
                    float2 av = *(const float2*)&sA[kk][rg * 2];
                    float  w  = sW[kk][c];
                    a0 = fmaf(av.x, w, a0);
                    a1 = fmaf(av.y, w, a1);
                }
                __syncthreads();
            }
            const int n = n0 + c;
            const float base = bq[n];
            #pragma unroll
            for (int i = 0; i < 2; i++) {
                int m = m0 + rg * 2 + i;
                float v = (i == 0 ? a0 : a1) + base
                        + pre_obs[((size_t)m * T + t) * EMBED + n];
                g_qh[m * EMBED + n] = fmaxf(v, 0.0f);
            }
        }
        grid_sync();

        // ======================= P4: qm -> sample ==========================
        {
            float (*sA4)[12] = (float(*)[12])smem;               // 64 x 12
            float (*sW4)[16] = (float(*)[16])(smem + 32 * 36);   // 64 x 16
            const int m0 = (bid & 15) * 8;
            const int n0 = (bid >> 4) * 16;
            float acc = 0.0f;
            for (int k0 = 0; k0 < EMBED; k0 += 64) {
                #pragma unroll
                for (int p = 0; p < 2; p++) {
                    int idx = tid + p * 256;
                    int kk = idx & 63, r = idx >> 6;
                    sA4[kk][r] = g_qh[(m0 + r) * EMBED + k0 + kk];
                }
                #pragma unroll
                for (int p = 0; p < 4; p++) {
                    int idx = tid + p * 256;
                    int kk = idx >> 4, cc = idx & 15;
                    sW4[kk][cc] = Wqm[(size_t)(k0 + kk) * STOCH + n0 + cc];
                }
                __syncthreads();
                if (tid < 128) {
                    int r = tid >> 4, cc = tid & 15;
                    #pragma unroll
                    for (int kk = 0; kk < 64; kk++)
                        acc = fmaf(sA4[kk][r], sW4[kk][cc], acc);
                }
                __syncthreads();
            }
            if (tid < 128) {
                int r = tid >> 4, cc = tid & 15;
                g_sample[(m0 + r) * STOCH + n0 + cc] = acc + bqm[n0 + cc];
            }
        }
        grid_sync();
    }
}

// ---------------------------------------------------------------------------
// Host driver: per level (2 -> 1 -> 0):
//   pre_ctx = dets_{l+1} @ Wp_ctx        (skipped at level 2: ctx == 0)
//   pre_obs = obs_l     @ Wq_obs
//   level_kernel (persistent scan)       -> 8 graph nodes total
// ---------------------------------------------------------------------------
extern "C" void kernel_launch(void* const* d_in, const int* in_sizes, int n_in,
                              void* d_out, int out_size)
{
    (void)in_sizes; (void)n_in; (void)out_size;
    const float* obs_arr[3] = {
        (const float*)d_in[0], (const float*)d_in[1], (const float*)d_in[2] };
    const float* Wp  = (const float*)d_in[3];
    const float* bp  = (const float*)d_in[4];
    const float* Wih = (const float*)d_in[5];
    const float* Whh = (const float*)d_in[6];
    const float* bih = (const float*)d_in[7];
    const float* bhh = (const float*)d_in[8];
    const float* Wq  = (const float*)d_in[9];
    const float* bq  = (const float*)d_in[10];
    const float* Wqm = (const float*)d_in[11];
    const float* bqm = (const float*)d_in[12];

    float *d1_, *d2_, *pc_, *po_;
    cudaGetSymbolAddress((void**)&d1_, g_dets1);
    cudaGetSymbolAddress((void**)&d2_, g_dets2);
    cudaGetSymbolAddress((void**)&pc_, g_pre_ctx);
    cudaGetSymbolAddress((void**)&po_, g_pre_obs);

    const int Ts[3] = { T0, T0 / 4, T0 / 16 };   // 256, 64, 16
    float* dets[3]  = { (float*)d_out, d1_, d2_ };

    for (int level = LVL - 1; level >= 0; level--) {
        const int T = Ts[level];
        const float* Wp_l  = Wp  + (size_t)level * (STOCH + DETER) * EMBED;
        const float* bp_l  = bp  + (size_t)level * EMBED;
        const float* Wih_l = Wih + (size_t)level * EMBED * G3;
        const float* Whh_l = Whh + (size_t)level * DETER * G3;
        const float* bih_l = bih + (size_t)level * G3;
        const float* bhh_l = bhh + (size_t)level * G3;
        const float* Wq_l  = Wq  + (size_t)level * (DETER + OBS_D) * EMBED;
        const float* bq_l  = bq  + (size_t)level * EMBED;
        const float* Wqm_l = Wqm + (size_t)level * EMBED * STOCH;
        const float* bqm_l = bqm + (size_t)level * STOCH;

        const float* pre_ctx = nullptr;
        int T1 = 1;
        if (level < LVL - 1) {
            T1 = Ts[level + 1];
            // pre_ctx[b*T1 + t1, :] = dets_{l+1}[b, t1, :] @ Wp_ctx  (K=1024)
            dim3 g(EMBED / 64, (BSZ * T1) / 64);
            gemm64_kernel<<<g, 128>>>(
                dets[level + 1], DETER,
                Wp_l + (size_t)STOCH * EMBED, EMBED,
                pc_, EMBED, DETER);
            pre_ctx = pc_;
        }

        // pre_obs[b*T + t, :] = obs[b, t, :] @ Wq_obs  (K=512)
        {
            dim3 g(EMBED / 64, (BSZ * T) / 64);
            gemm64_kernel<<<g, 128>>>(
                obs_arr[level], OBS_D,
                Wq_l + (size_t)DETER * EMBED, EMBED,
                po_, EMBED, OBS_D);
        }

        level_kernel<<<NB, 256>>>(
            dets[level], T, pre_ctx, T1, po_,
            Wp_l, bp_l, Wih_l, Whh_l, bih_l, bhh_l,
            Wq_l, bq_l, Wqm_l, bqm_l);
    }
}

// round 8
// speedup vs baseline: 1.1590x; 1.1590x over previous
#include <cuda_runtime.h>
#include <cstdint>
#include <cstddef>
#include <math.h>

#define LVL   3
#define BSZ   128
#define T0    256
#define STOCH 128
#define DETER 1024
#define EMBED 512
#define OBS_D 512
#define G3    (3*DETER)   // 3072
#define NB    128          // persistent grid (<=148 SMs, all co-resident)

typedef unsigned long long u64;

// ---------------------------------------------------------------------------
// Static device scratch (no allocations allowed).
// ---------------------------------------------------------------------------
__device__ float g_h[BSZ * EMBED];
__device__ float g_qh[BSZ * EMBED];
__device__ float g_dets1[BSZ * 64 * DETER];     // level-1 dets
__device__ float g_dets2[BSZ * 16 * DETER];     // level-2 dets
__device__ float g_pre_ctx[BSZ * 64 * EMBED];   // ctx @ Wp_ctx
__device__ float g_pre_obs[BSZ * T0 * EMBED];   // obs @ Wq_obs
__device__ float g_Wcomb[EMBED * EMBED];        // Wqm @ Wp_sample (per level)
__device__ float g_bvec[EMBED];                 // bp + bqm @ Wp_sample
__device__ unsigned int g_bar_count;
__device__ unsigned int g_bar_gen;

// ---------------------------------------------------------------------------
// Packed fp32 helpers (fma.rn.f32x2 is only reachable via PTX; bit-exact fp32)
// ---------------------------------------------------------------------------
__device__ __forceinline__ void ffma2(u64& d, u64 a, u64 b) {
    asm("fma.rn.f32x2 %0, %1, %2, %0;" : "+l"(d) : "l"(a), "l"(b));
}
__device__ __forceinline__ u64 bcast2(float x) {
    u64 r; asm("mov.b64 %0, {%1, %1};" : "=l"(r) : "f"(x)); return r;
}
__device__ __forceinline__ float2 unpack2(u64 v) {
    float lo, hi;
    asm("mov.b64 {%0, %1}, %2;" : "=f"(lo), "=f"(hi) : "l"(v));
    return make_float2(lo, hi);
}

// ---------------------------------------------------------------------------
// Software grid barrier (monotonic generation). NB blocks all co-resident.
// ---------------------------------------------------------------------------
__device__ __forceinline__ void grid_sync() {
    __syncthreads();
    if (threadIdx.x == 0) {
        volatile unsigned int* genp = &g_bar_gen;
        unsigned int g = *genp;
        __threadfence();
        unsigned int a = atomicAdd(&g_bar_count, 1u);
        if (a == NB - 1u) {
            atomicExch(&g_bar_count, 0u);
            __threadfence();
            atomicAdd(&g_bar_gen, 1u);
        } else {
            while (*genp == g) { }
        }
        __threadfence();
    }
    __syncthreads();
}

// ---------------------------------------------------------------------------
// Precompute GEMM: C[M,N] = A[M,K] @ W[K,N]
// ---------------------------------------------------------------------------
__global__ __launch_bounds__(128) void gemm64_kernel(
    const float* __restrict__ A, int lda,
    const float* __restrict__ W, int ldw,
    float* __restrict__ C, int ldc, int K)
{
    constexpr int BM = 64, BN = 64, BK = 16, TM = 4, TN = 8;
    __shared__ float sA[BK][BM + 4];
    __shared__ float sW[BK][BN];

    const int tid  = threadIdx.x;
    const int tx   = tid & 7;
    const int ty   = tid >> 3;
    const int row0 = blockIdx.y * BM;
    const int col0 = blockIdx.x * BN;

    float acc[TM][TN];
    #pragma unroll
    for (int i = 0; i < TM; i++)
        #pragma unroll
        for (int j = 0; j < TN; j++) acc[i][j] = 0.0f;

    for (int k0 = 0; k0 < K; k0 += BK) {
        #pragma unroll
        for (int p = 0; p < 8; p++) {
            int i  = tid + p * 128;
            int kk = i & 15, r = i >> 4;
            sA[kk][r] = A[(size_t)(row0 + r) * lda + (k0 + kk)];
        }
        #pragma unroll
        for (int p = 0; p < 8; p++) {
            int i  = tid + p * 128;
            int kk = i >> 6, cc = i & 63;
            sW[kk][cc] = W[(size_t)(k0 + kk) * ldw + (col0 + cc)];
        }
        __syncthreads();
        #pragma unroll
        for (int kk = 0; kk < BK; kk++) {
            float4 av = *(const float4*)&sA[kk][ty * TM];
            float4 w0 = *(const float4*)&sW[kk][tx * TN];
            float4 w1 = *(const float4*)&sW[kk][tx * TN + 4];
            float a[TM] = {av.x, av.y, av.z, av.w};
            float w[TN] = {w0.x, w0.y, w0.z, w0.w, w1.x, w1.y, w1.z, w1.w};
            #pragma unroll
            for (int i = 0; i < TM; i++)
                #pragma unroll
                for (int j = 0; j < TN; j++)
                    acc[i][j] = fmaf(a[i], w[j], acc[i][j]);
        }
        __syncthreads();
    }

    #pragma unroll
    for (int i = 0; i < TM; i++) {
        int m  = row0 + ty * TM + i;
        int n0 = col0 + tx * TN;
        float4 o0 = {acc[i][0], acc[i][1], acc[i][2], acc[i][3]};
        float4 o1 = {acc[i][4], acc[i][5], acc[i][6], acc[i][7]};
        *(float4*)&C[(size_t)m * ldc + n0]     = o0;
        *(float4*)&C[(size_t)m * ldc + n0 + 4] = o1;
    }
}

// bvec[n] = bp[n] + sum_s bqm[s] * Wp_sample[s, n]
__global__ void bvec_kernel(const float* __restrict__ Wp,
                            const float* __restrict__ bp,
                            const float* __restrict__ bqm)
{
    const int n = blockIdx.x * blockDim.x + threadIdx.x;
    if (n >= EMBED) return;
    float s = bp[n];
    for (int k = 0; k < STOCH; k++)
        s = fmaf(bqm[k], Wp[(size_t)k * EMBED + n], s);
    g_bvec[n] = s;
}

// ---------------------------------------------------------------------------
// Persistent per-level scan. 3 phases / 3 grid barriers per step:
//   P1: h  = relu(qh_prev @ Wcomb + bvec + pre_ctx)   (t=0: relu(bp+pre_ctx))
//   P2: gi = h @ Wih; gh = det_old @ Whh; GRU combine -> det_new
//   P3: qh = relu(det_new @ Wq_det + bq + pre_obs)
// Double-buffered smem, packed f32x2 FMA throughout.
// ---------------------------------------------------------------------------
__global__ __launch_bounds__(256, 1) void level_kernel(
    float* __restrict__ dets, int T,
    const float* __restrict__ pre_ctx, int T1,
    const float* __restrict__ pre_obs,
    const float* __restrict__ Wih, const float* __restrict__ Whh,
    const float* __restrict__ bih, const float* __restrict__ bhh,
    const float* __restrict__ Wq,  const float* __restrict__ bq,
    const float* __restrict__ bp)
{
    __shared__ __align__(16) float sA[2][32][34];   // [buf][kk][row]
    __shared__ __align__(16) float sW[2][32][96];   // [buf][kk][col]

    const int tid = threadIdx.x;
    const int bid = blockIdx.x;
    const int rg  = tid >> 5;      // warp id 0..7
    const int c   = tid & 31;      // lane
    const size_t ldd = (size_t)T * DETER;

    const int m0g = (bid & 3) * 32;      // P2 tile: 32 m x 32 j (x3 segs x2 mats)
    const int j0  = (bid >> 2) * 32;
    const int m0s = (bid & 7) * 16;      // P1/P3 tile: 16 m x 32 n
    const int n0  = (bid >> 3) * 32;
    const int n   = n0 + c;

    for (int t = 0; t < T; t++) {
        // ======================= P1: h =====================================
        {
            u64 acc = 0ull;
            if (t > 0) {
                float rA[2], rW[4];
                #pragma unroll
                for (int p = 0; p < 2; p++)
                    rA[p] = g_qh[(m0s + rg + 8*p) * EMBED + c];
                #pragma unroll
                for (int p = 0; p < 4; p++)
                    rW[p] = g_Wcomb[(size_t)(rg + 8*p) * EMBED + n];
                #pragma unroll
                for (int p = 0; p < 2; p++) sA[0][c][rg + 8*p] = rA[p];
                #pragma unroll
                for (int p = 0; p < 4; p++) sW[0][rg + 8*p][c] = rW[p];
                __syncthreads();

                #pragma unroll 1
                for (int ch = 0; ch < 16; ch++) {
                    const int cur = ch & 1;
                    const bool more = (ch + 1 < 16);
                    if (more) {
                        const int k0 = (ch + 1) * 32;
                        #pragma unroll
                        for (int p = 0; p < 2; p++)
                            rA[p] = g_qh[(m0s + rg + 8*p) * EMBED + k0 + c];
                        #pragma unroll
                        for (int p = 0; p < 4; p++)
                            rW[p] = g_Wcomb[(size_t)(k0 + rg + 8*p) * EMBED + n];
                    }
                    #pragma unroll
                    for (int kk = 0; kk < 32; kk++) {
                        u64 a = *(const u64*)&sA[cur][kk][rg * 2];
                        ffma2(acc, a, bcast2(sW[cur][kk][c]));
                    }
                    if (more) {
                        const int nb_ = cur ^ 1;
                        #pragma unroll
                        for (int p = 0; p < 2; p++) sA[nb_][c][rg + 8*p] = rA[p];
                        #pragma unroll
                        for (int p = 0; p < 4; p++) sW[nb_][rg + 8*p][c] = rW[p];
                    }
                    __syncthreads();
                }
            }
            float2 av = unpack2(acc);
            const int mA = m0s + rg * 2, mB = mA + 1;
            float pc0 = 0.f, pc1 = 0.f;
            if (pre_ctx) {
                const int tt = t & (T1 - 1);
                pc0 = pre_ctx[((size_t)mA * T1 + tt) * EMBED + n];
                pc1 = pre_ctx[((size_t)mB * T1 + tt) * EMBED + n];
            }
            const float bb = (t == 0) ? bp[n] : g_bvec[n];
            g_h[mA * EMBED + n] = fmaxf(av.x + bb + pc0, 0.f);
            g_h[mB * EMBED + n] = fmaxf(av.y + bb + pc1, 0.f);
        }
        grid_sync();

        // ============ P2: gates (gi & gh) + GRU combine =====================
        {
            u64 ai[3][2] = {{0ull,0ull},{0ull,0ull},{0ull,0ull}};
            u64 ah[3][2] = {{0ull,0ull},{0ull,0ull},{0ull,0ull}};

            const int nparts = (t > 0) ? 2 : 1;
            for (int part = 0; part < nparts; part++) {
                const float* Ab = (part == 0) ? g_h
                                              : (dets + (size_t)(t - 1) * DETER);
                const size_t As = (part == 0) ? (size_t)EMBED : ldd;
                const float* Wm = (part == 0) ? Wih : Whh;
                const int nch   = (part == 0) ? 16 : 32;
                u64 (*acc)[2]   = (part == 0) ? ai : ah;

                float rA[4], rW[12];
                #pragma unroll
                for (int p = 0; p < 4; p++)
                    rA[p] = Ab[(size_t)(m0g + rg + 8*p) * As + c];
                #pragma unroll
                for (int s = 0; s < 3; s++)
                    #pragma unroll
                    for (int p = 0; p < 4; p++)
                        rW[s*4+p] = Wm[(size_t)(rg + 8*p) * G3 + s * DETER + j0 + c];
                #pragma unroll
                for (int p = 0; p < 4; p++) sA[0][c][rg + 8*p] = rA[p];
                #pragma unroll
                for (int s = 0; s < 3; s++)
                    #pragma unroll
                    for (int p = 0; p < 4; p++)
                        sW[0][rg + 8*p][s*32 + c] = rW[s*4+p];
                __syncthreads();

                #pragma unroll 1
                for (int ch = 0; ch < nch; ch++) {
                    const int cur = ch & 1;
                    const bool more = (ch + 1 < nch);
                    if (more) {
                        const int k0 = (ch + 1) * 32;
                        #pragma unroll
                        for (int p = 0; p < 4; p++)
                            rA[p] = Ab[(size_t)(m0g + rg + 8*p) * As + k0 + c];
                        #pragma unroll
                        for (int s = 0; s < 3; s++)
                            #pragma unroll
                            for (int p = 0; p < 4; p++)
                                rW[s*4+p] = Wm[(size_t)(k0 + rg + 8*p) * G3
                                               + s * DETER + j0 + c];
                    }
                    #pragma unroll
                    for (int kk = 0; kk < 32; kk++) {
                        u64 a0 = *(const u64*)&sA[cur][kk][rg * 4];
                        u64 a1 = *(const u64*)&sA[cur][kk][rg * 4 + 2];
                        #pragma unroll
                        for (int s = 0; s < 3; s++) {
                            u64 wp = bcast2(sW[cur][kk][s*32 + c]);
                            ffma2(acc[s][0], a0, wp);
                            ffma2(acc[s][1], a1, wp);
                        }
                    }
                    if (more) {
                        const int nb_ = cur ^ 1;
                        #pragma unroll
                        for (int p = 0; p < 4; p++) sA[nb_][c][rg + 8*p] = rA[p];
                        #pragma unroll
                        for (int s = 0; s < 3; s++)
                            #pragma unroll
                            for (int p = 0; p < 4; p++)
                                sW[nb_][rg + 8*p][s*32 + c] = rW[s*4+p];
                    }
                    __syncthreads();
                }
            }

            // GRU combine epilogue -> det_new
            float* dnew = dets + (size_t)t * DETER;
            const float* dold = dets + (size_t)(t - 1) * DETER;
            const int j = j0 + c;
            const float br   = bih[j] + bhh[j];
            const float bz   = bih[DETER + j] + bhh[DETER + j];
            const float bin_ = bih[2 * DETER + j];
            const float bhn  = bhh[2 * DETER + j];
            #pragma unroll
            for (int pr = 0; pr < 2; pr++) {
                float2 vr = unpack2(ai[0][pr]); float2 hr = unpack2(ah[0][pr]);
                float2 vz = unpack2(ai[1][pr]); float2 hz = unpack2(ah[1][pr]);
                float2 vn = unpack2(ai[2][pr]); float2 hn = unpack2(ah[2][pr]);
                #pragma unroll
                for (int q = 0; q < 2; q++) {
                    const int m = m0g + rg * 4 + pr * 2 + q;
                    float gr  = (q ? vr.y + hr.y : vr.x + hr.x) + br;
                    float gz  = (q ? vz.y + hz.y : vz.x + hz.x) + bz;
                    float inn = (q ? vn.y : vn.x) + bin_;
                    float hnn = (q ? hn.y : hn.x) + bhn;
                    float rr = 1.f / (1.f + expf(-gr));
                    float zz = 1.f / (1.f + expf(-gz));
                    float nn = tanhf(inn + rr * hnn);
                    float d  = (t > 0) ? dold[(size_t)m * ldd + j] : 0.f;
                    dnew[(size_t)m * ldd + j] = (1.f - zz) * nn + zz * d;
                }
            }
        }
        grid_sync();

        // ======================= P3: qh ====================================
        {
            const float* dnew = dets + (size_t)t * DETER;
            u64 acc = 0ull;
            float rA[2], rW[4];
            #pragma unroll
            for (int p = 0; p < 2; p++)
                rA[p] = dnew[(size_t)(m0s + rg + 8*p) * ldd + c];
            #pragma unroll
            for (int p = 0; p < 4; p++)
                rW[p] = Wq[(size_t)(rg + 8*p) * EMBED + n];
            #pragma unroll
            for (int p = 0; p < 2; p++) sA[0][c][rg + 8*p] = rA[p];
            #pragma unroll
            for (int p = 0; p < 4; p++) sW[0][rg + 8*p][c] = rW[p];
            __syncthreads();

            #pragma unroll 1
            for (int ch = 0; ch < 32; ch++) {
                const int cur = ch & 1;
                const bool more = (ch + 1 < 32);
                if (more) {
                    const int k0 = (ch + 1) * 32;
                    #pragma unroll
                    for (int p = 0; p < 2; p++)
                        rA[p] = dnew[(size_t)(m0s + rg + 8*p) * ldd + k0 + c];
                    #pragma unroll
                    for (int p = 0; p < 4; p++)
                        rW[p] = Wq[(size_t)(k0 + rg + 8*p) * EMBED + n];
                }
                #pragma unroll
                for (int kk = 0; kk < 32; kk++) {
                    u64 a = *(const u64*)&sA[cur][kk][rg * 2];
                    ffma2(acc, a, bcast2(sW[cur][kk][c]));
                }
                if (more) {
                    const int nb_ = cur ^ 1;
                    #pragma unroll
                    for (int p = 0; p < 2; p++) sA[nb_][c][rg + 8*p] = rA[p];
                    #pragma unroll
                    for (int p = 0; p < 4; p++) sW[nb_][rg + 8*p][c] = rW[p];
                }
                __syncthreads();
            }
            float2 av = unpack2(acc);
            const int mA = m0s + rg * 2, mB = mA + 1;
            const float bb = bq[n];
            float o0 = av.x + bb + pre_obs[((size_t)mA * T + t) * EMBED + n];
            float o1 = av.y + bb + pre_obs[((size_t)mB * T + t) * EMBED + n];
            g_qh[mA * EMBED + n] = fmaxf(o0, 0.f);
            g_qh[mB * EMBED + n] = fmaxf(o1, 0.f);
        }
        grid_sync();
    }
}

// ---------------------------------------------------------------------------
// Host driver
// ---------------------------------------------------------------------------
extern "C" void kernel_launch(void* const* d_in, const int* in_sizes, int n_in,
                              void* d_out, int out_size)
{
    (void)in_sizes; (void)n_in; (void)out_size;
    const float* obs_arr[3] = {
        (const float*)d_in[0], (const float*)d_in[1], (const float*)d_in[2] };
    const float* Wp  = (const float*)d_in[3];
    const float* bp  = (const float*)d_in[4];
    const float* Wih = (const float*)d_in[5];
    const float* Whh = (const float*)d_in[6];
    const float* bih = (const float*)d_in[7];
    const float* bhh = (const float*)d_in[8];
    const float* Wq  = (const float*)d_in[9];
    const float* bq  = (const float*)d_in[10];
    const float* Wqm = (const float*)d_in[11];
    const float* bqm = (const float*)d_in[12];

    float *d1_, *d2_, *pc_, *po_, *wc_;
    cudaGetSymbolAddress((void**)&d1_, g_dets1);
    cudaGetSymbolAddress((void**)&d2_, g_dets2);
    cudaGetSymbolAddress((void**)&pc_, g_pre_ctx);
    cudaGetSymbolAddress((void**)&po_, g_pre_obs);
    cudaGetSymbolAddress((void**)&wc_, g_Wcomb);

    const int Ts[3] = { T0, T0 / 4, T0 / 16 };   // 256, 64, 16
    float* dets[3]  = { (float*)d_out, d1_, d2_ };

    for (int level = LVL - 1; level >= 0; level--) {
        const int T = Ts[level];
        const float* Wp_l  = Wp  + (size_t)level * (STOCH + DETER) * EMBED;
        const float* bp_l  = bp  + (size_t)level * EMBED;
        const float* Wih_l = Wih + (size_t)level * EMBED * G3;
        const float* Whh_l = Whh + (size_t)level * DETER * G3;
        const float* bih_l = bih + (size_t)level * G3;
        const float* bhh_l = bhh + (size_t)level * G3;
        const float* Wq_l  = Wq  + (size_t)level * (DETER + OBS_D) * EMBED;
        const float* bq_l  = bq  + (size_t)level * EMBED;
        const float* Wqm_l = Wqm + (size_t)level * EMBED * STOCH;
        const float* bqm_l = bqm + (size_t)level * STOCH;

        // Wcomb = Wqm @ Wp_sample   (512x512, K=128)
        {
            dim3 g(EMBED / 64, EMBED / 64);
            gemm64_kernel<<<g, 128>>>(Wqm_l, STOCH, Wp_l, EMBED,
                                      wc_, EMBED, STOCH);
        }
        // bvec = bp + bqm @ Wp_sample
        bvec_kernel<<<2, 256>>>(Wp_l, bp_l, bqm_l);

        const float* pre_ctx = nullptr;
        int T1 = 1;
        if (level < LVL - 1) {
            T1 = Ts[level + 1];
            dim3 g(EMBED / 64, (BSZ * T1) / 64);
            gemm64_kernel<<<g, 128>>>(
                dets[level + 1], DETER,
                Wp_l + (size_t)STOCH * EMBED, EMBED,
                pc_, EMBED, DETER);
            pre_ctx = pc_;
        }

        // pre_obs = obs @ Wq_obs  (K=512)
        {
            dim3 g(EMBED / 64, (BSZ * T) / 64);
            gemm64_kernel<<<g, 128>>>(
                obs_arr[level], OBS_D,
                Wq_l + (size_t)DETER * EMBED, EMBED,
                po_, EMBED, OBS_D);
        }

        level_kernel<<<NB, 256>>>(
            dets[level], T, pre_ctx, T1, po_,
            Wih_l, Whh_l, bih_l, bhh_l, Wq_l, bq_l, bp_l);
    }
}